// round 1
// baseline (speedup 1.0000x reference)
#include <cuda_runtime.h>

#define BATCH 16
#define H 256
#define W 256
#define HW (H*W)
#define NTAP 25
#define RAD 2
#define NITER 10

#define TW 32
#define TH 8
#define HALOW (TW + 2*RAD)   // 36
#define HALOH (TH + 2*RAD)   // 12

// Scratch (no cudaMalloc allowed): ~218 MB of __device__ globals.
__device__ float g_kA[BATCH * NTAP * HW];   // feature kernel        (~105 MB)
__device__ float g_kB[BATCH * NTAP * HW];   // feature*depth kernel  (~105 MB)
__device__ float g_xA[2][BATCH * HW];       // chain A state (ping-pong)
__device__ float g_xB[2][BATCH * HW];       // chain B state (ping-pong)
__device__ unsigned int g_cnt[BATCH * 8];   // per batch: {inter,union} x 4 masks

// ---------------------------------------------------------------------------
// Init: x0 = clip(seg, 0.1, 0.9) for both chains; zero IoU counters.
// ---------------------------------------------------------------------------
__global__ __launch_bounds__(256) void mf_init(const float* __restrict__ seg) {
    int i = blockIdx.x * 256 + threadIdx.x;
    if (i < BATCH * HW) {
        float x = fminf(fmaxf(seg[i], 0.1f), 0.9f);
        g_xA[0][i] = x;
        g_xB[0][i] = x;
    }
    if (blockIdx.x == 0 && threadIdx.x < BATCH * 8)
        g_cnt[threadIdx.x] = 0u;
}

// ---------------------------------------------------------------------------
// Build the two 25-tap kernels per pixel.
// kernel  = exp(-sum_c (fm_n - fm_c)^2 / 0.02)  (fm = feature + 10; OOB -> 0)
// kernelD = kernel * exp(-(d_n - d_c)^2 / 0.02) (OOB d -> 0)
// Layout: g_k*[ ((b*25 + j) * HW) + hw ]  (coalesced over hw)
// ---------------------------------------------------------------------------
__global__ __launch_bounds__(256) void build_kernels(
    const float* __restrict__ fm, const float* __restrict__ depth) {
    __shared__ float sf0[HALOH][HALOW];
    __shared__ float sf1[HALOH][HALOW];
    __shared__ float sf2[HALOH][HALOW];
    __shared__ float sd [HALOH][HALOW];

    int b   = blockIdx.z;
    int ty0 = blockIdx.y * TH;
    int tx0 = blockIdx.x * TW;
    int tid = threadIdx.y * TW + threadIdx.x;

    for (int i = tid; i < HALOH * HALOW; i += TH * TW) {
        int hy = i / HALOW, hx = i % HALOW;
        int gy = ty0 + hy - RAD, gx = tx0 + hx - RAD;
        float f0 = 0.f, f1 = 0.f, f2 = 0.f, d = 0.f;
        if (gy >= 0 && gy < H && gx >= 0 && gx < W) {
            int idx = gy * W + gx;
            f0 = fm[(b * 3 + 0) * HW + idx] + 10.f;
            f1 = fm[(b * 3 + 1) * HW + idx] + 10.f;
            f2 = fm[(b * 3 + 2) * HW + idx] + 10.f;
            d  = depth[b * HW + idx];
        }
        sf0[hy][hx] = f0; sf1[hy][hx] = f1; sf2[hy][hx] = f2; sd[hy][hx] = d;
    }
    __syncthreads();

    int ly = threadIdx.y, lx = threadIdx.x;
    int gy = ty0 + ly, gx = tx0 + lx;
    int hw = gy * W + gx;

    float c0 = sf0[ly + RAD][lx + RAD];
    float c1 = sf1[ly + RAD][lx + RAD];
    float c2 = sf2[ly + RAD][lx + RAD];
    float cd = sd [ly + RAD][lx + RAD];

    float* kA = g_kA + (b * NTAP) * HW + hw;
    float* kB = g_kB + (b * NTAP) * HW + hw;

    #pragma unroll
    for (int j = 0; j < NTAP; j++) {
        int kh = j / 5, kw = j % 5;
        float d0 = sf0[ly + kh][lx + kw] - c0;
        float d1 = sf1[ly + kh][lx + kw] - c1;
        float d2 = sf2[ly + kh][lx + kw] - c2;
        float s  = d0 * d0 + d1 * d1 + d2 * d2;
        float k  = expf(-(s / 0.02f));
        float dd = sd[ly + kh][lx + kw] - cd;
        float ks = k * expf(-((dd * dd) / 0.02f));
        kA[j * HW] = k;
        kB[j * HW] = ks;
    }
}

// ---------------------------------------------------------------------------
// One mean-field iteration, both chains fused.
// aggre_c = exp( sum_j k_j * log p_c(n_j) );  padding contributes 0 (u=0).
// ---------------------------------------------------------------------------
__global__ __launch_bounds__(256) void mf_iter(int src) {
    __shared__ float sA1[HALOH][HALOW];  // log(x)     chain A
    __shared__ float sA0[HALOH][HALOW];  // log(1-x)   chain A
    __shared__ float sB1[HALOH][HALOW];
    __shared__ float sB0[HALOH][HALOW];

    int b   = blockIdx.z;
    int ty0 = blockIdx.y * TH;
    int tx0 = blockIdx.x * TW;
    int tid = threadIdx.y * TW + threadIdx.x;

    const float* xAs = g_xA[src];
    const float* xBs = g_xB[src];
    float*       xAd = g_xA[src ^ 1];
    float*       xBd = g_xB[src ^ 1];

    for (int i = tid; i < HALOH * HALOW; i += TH * TW) {
        int hy = i / HALOW, hx = i % HALOW;
        int gy = ty0 + hy - RAD, gx = tx0 + hx - RAD;
        float a1 = 0.f, a0 = 0.f, b1 = 0.f, b0 = 0.f;
        if (gy >= 0 && gy < H && gx >= 0 && gx < W) {
            int idx = b * HW + gy * W + gx;
            float xa = xAs[idx];
            float xb = xBs[idx];
            a1 = logf(xa); a0 = logf(1.0f - xa);
            b1 = logf(xb); b0 = logf(1.0f - xb);
        }
        sA1[hy][hx] = a1; sA0[hy][hx] = a0;
        sB1[hy][hx] = b1; sB0[hy][hx] = b0;
    }
    __syncthreads();

    int ly = threadIdx.y, lx = threadIdx.x;
    int gy = ty0 + ly, gx = tx0 + lx;
    int hw = gy * W + gx;

    const float* kA = g_kA + (b * NTAP) * HW + hw;
    const float* kB = g_kB + (b * NTAP) * HW + hw;

    float S1A = 0.f, S0A = 0.f, S1B = 0.f, S0B = 0.f;
    #pragma unroll
    for (int j = 0; j < NTAP; j++) {
        int kh = j / 5, kw = j % 5;
        float wA = __ldg(kA + j * HW);
        float wB = __ldg(kB + j * HW);
        S1A += wA * sA1[ly + kh][lx + kw];
        S0A += wA * sA0[ly + kh][lx + kw];
        S1B += wB * sB1[ly + kh][lx + kw];
        S0B += wB * sB0[ly + kh][lx + kw];
    }

    {
        float a1 = expf(S1A), a0 = expf(S0A);
        float x = a1 / (1e-6f + (a0 + a1));
        xAd[b * HW + hw] = fminf(fmaxf(x, 0.1f), 0.9f);
    }
    {
        float a1 = expf(S1B), a0 = expf(S0B);
        float x = a1 / (1e-6f + (a0 + a1));
        xBd[b * HW + hw] = fminf(fmaxf(x, 0.1f), 0.9f);
    }
}

// ---------------------------------------------------------------------------
// Finalize: write rgb_mask, accumulate per-batch inter/union for 4 masks.
// ---------------------------------------------------------------------------
__global__ __launch_bounds__(256) void finalize(
    const float* __restrict__ seg, const float* __restrict__ targets,
    const float* __restrict__ sam, int src, float* __restrict__ out_mask) {
    int b = blockIdx.y;
    int p = blockIdx.x * 256 + threadIdx.x;
    int i = b * HW + p;

    bool t  = (targets[i] != 0.f);
    bool m0 = (seg[i]       > 0.5f);
    bool m1 = (g_xA[src][i] > 0.5f);
    bool m2 = (g_xB[src][i] > 0.5f);
    bool m3 = (sam[i] != 0.f);

    out_mask[i] = m1 ? 1.f : 0.f;

    __shared__ unsigned int c[8];
    if (threadIdx.x < 8) c[threadIdx.x] = 0u;
    __syncthreads();

    bool preds[4] = {m0, m1, m2, m3};
    int lane = threadIdx.x & 31;
    #pragma unroll
    for (int m = 0; m < 4; m++) {
        unsigned bi = __ballot_sync(0xFFFFFFFFu, t && preds[m]);
        unsigned bu = __ballot_sync(0xFFFFFFFFu, t || preds[m]);
        if (lane == 0) {
            atomicAdd(&c[2 * m + 0], (unsigned)__popc(bi));
            atomicAdd(&c[2 * m + 1], (unsigned)__popc(bu));
        }
    }
    __syncthreads();
    if (threadIdx.x < 8)
        atomicAdd(&g_cnt[b * 8 + threadIdx.x], c[threadIdx.x]);
}

__global__ void iou_kernel(float* __restrict__ out_ious) {
    int m = threadIdx.x;
    if (m < 4) {
        float s = 0.f;
        for (int b = 0; b < BATCH; b++) {
            float inter = (float)g_cnt[b * 8 + 2 * m + 0];
            float uni   = (float)g_cnt[b * 8 + 2 * m + 1];
            s += inter / (uni + 1e-6f);
        }
        out_ious[m] = s * (1.0f / (float)BATCH);
    }
}

// ---------------------------------------------------------------------------
extern "C" void kernel_launch(void* const* d_in, const int* in_sizes, int n_in,
                              void* d_out, int out_size) {
    const float* fm      = (const float*)d_in[0];  // (16,3,256,256)
    const float* seg     = (const float*)d_in[1];  // (16,256,256)
    const float* depth   = (const float*)d_in[2];
    const float* targets = (const float*)d_in[3];
    const float* sam     = (const float*)d_in[4];
    float* out = (float*)d_out;

    dim3 blk(TW, TH);
    dim3 grd(W / TW, H / TH, BATCH);

    mf_init<<<(BATCH * HW + 255) / 256, 256>>>(seg);
    build_kernels<<<grd, blk>>>(fm, depth);

    int src = 0;
    for (int it = 0; it < NITER; it++) {
        mf_iter<<<grd, blk>>>(src);
        src ^= 1;
    }

    finalize<<<dim3(HW / 256, BATCH), 256>>>(seg, targets, sam, src, out);
    iou_kernel<<<1, 32>>>(out + (out_size - 4));
}

// round 2
// speedup vs baseline: 1.0372x; 1.0372x over previous
#include <cuda_runtime.h>

#define BATCH 16
#define H 256
#define W 256
#define HW (H*W)
#define NPLANE 12          // unique off-center taps (center weight == 1)
#define RAD 2
#define NITER 10
#define GB 4               // batches per mf_iter launch group (L2 blocking)

#define TW 32
#define TH 8
#define HALOW (TW + 2*RAD)   // 36
#define HALOH (TH + 2*RAD)   // 12

// Scratch (no cudaMalloc allowed): ~109 MB of __device__ globals.
__device__ float g_kA[BATCH * NPLANE * HW];   // feature kernel planes       (~50 MB)
__device__ float g_kB[BATCH * NPLANE * HW];   // feature*depth kernel planes (~50 MB)
__device__ float g_xA[2][BATCH * HW];         // chain A state (ping-pong)
__device__ float g_xB[2][BATCH * HW];         // chain B state (ping-pong)
__device__ unsigned int g_cnt[BATCH * 8];     // per batch: {inter,union} x 4 masks

// ---------------------------------------------------------------------------
// Init: x0 = clip(seg, 0.1, 0.9) for both chains; zero IoU counters.
// ---------------------------------------------------------------------------
__global__ __launch_bounds__(256) void mf_init(const float* __restrict__ seg) {
    int i = blockIdx.x * 256 + threadIdx.x;
    if (i < BATCH * HW) {
        float x = fminf(fmaxf(seg[i], 0.1f), 0.9f);
        g_xA[0][i] = x;
        g_xB[0][i] = x;
    }
    if (blockIdx.x == 0 && threadIdx.x < BATCH * 8)
        g_cnt[threadIdx.x] = 0u;
}

// ---------------------------------------------------------------------------
// Build the 12 unique-tap weight planes per batch (taps 0..11; mirror taps
// 24-t are shifted copies by symmetry, center tap is exactly 1).
// kernel  = exp(-sum_c (fm_n - fm_c)^2 / 0.02)  (fm = feature + 10; OOB -> 0)
// kernelD = kernel * exp(-(d_n - d_c)^2 / 0.02)
// Layout: g_k*[ ((b*12 + t) * HW) + hw ]  (coalesced over hw)
// ---------------------------------------------------------------------------
__global__ __launch_bounds__(256) void build_kernels(
    const float* __restrict__ fm, const float* __restrict__ depth) {
    __shared__ float sf0[HALOH][HALOW];
    __shared__ float sf1[HALOH][HALOW];
    __shared__ float sf2[HALOH][HALOW];
    __shared__ float sd [HALOH][HALOW];

    int b   = blockIdx.z;
    int ty0 = blockIdx.y * TH;
    int tx0 = blockIdx.x * TW;
    int tid = threadIdx.y * TW + threadIdx.x;

    for (int i = tid; i < HALOH * HALOW; i += TH * TW) {
        int hy = i / HALOW, hx = i % HALOW;
        int gy = ty0 + hy - RAD, gx = tx0 + hx - RAD;
        float f0 = 0.f, f1 = 0.f, f2 = 0.f, d = 0.f;
        if (gy >= 0 && gy < H && gx >= 0 && gx < W) {
            int idx = gy * W + gx;
            f0 = fm[(b * 3 + 0) * HW + idx] + 10.f;
            f1 = fm[(b * 3 + 1) * HW + idx] + 10.f;
            f2 = fm[(b * 3 + 2) * HW + idx] + 10.f;
            d  = depth[b * HW + idx];
        }
        sf0[hy][hx] = f0; sf1[hy][hx] = f1; sf2[hy][hx] = f2; sd[hy][hx] = d;
    }
    __syncthreads();

    int ly = threadIdx.y, lx = threadIdx.x;
    int gy = ty0 + ly, gx = tx0 + lx;
    int hw = gy * W + gx;

    float c0 = sf0[ly + RAD][lx + RAD];
    float c1 = sf1[ly + RAD][lx + RAD];
    float c2 = sf2[ly + RAD][lx + RAD];
    float cd = sd [ly + RAD][lx + RAD];

    float* kA = g_kA + (b * NPLANE) * HW + hw;
    float* kB = g_kB + (b * NPLANE) * HW + hw;

    #pragma unroll
    for (int t = 0; t < NPLANE; t++) {
        int kh = t / 5, kw = t % 5;
        float d0 = sf0[ly + kh][lx + kw] - c0;
        float d1 = sf1[ly + kh][lx + kw] - c1;
        float d2 = sf2[ly + kh][lx + kw] - c2;
        float s  = d0 * d0 + d1 * d1 + d2 * d2;
        float k  = expf(-(s / 0.02f));
        float dd = sd[ly + kh][lx + kw] - cd;
        float ks = k * expf(-((dd * dd) / 0.02f));
        kA[t * HW] = k;
        kB[t * HW] = ks;
    }
}

// ---------------------------------------------------------------------------
// One mean-field iteration, both chains fused, symmetric-tap formulation:
//   S(p) = L(p)  [center, w=1]
//        + sum_{t<12} P_t(p)   * L(p + o_t)      (tap t)
//        + sum_{t<12} P_t(p-o) * L(p - o_t)      (mirror tap 24-t)
// P_t(p-o) read out-of-image is 0 (predicated load), matching zero-pad unfold.
// ---------------------------------------------------------------------------
__global__ __launch_bounds__(256) void mf_iter(int src, int b0) {
    __shared__ float sA1[HALOH][HALOW];  // log(x)     chain A
    __shared__ float sA0[HALOH][HALOW];  // log(1-x)   chain A
    __shared__ float sB1[HALOH][HALOW];
    __shared__ float sB0[HALOH][HALOW];

    int b   = b0 + blockIdx.z;
    int ty0 = blockIdx.y * TH;
    int tx0 = blockIdx.x * TW;
    int tid = threadIdx.y * TW + threadIdx.x;

    const float* xAs = g_xA[src];
    const float* xBs = g_xB[src];
    float*       xAd = g_xA[src ^ 1];
    float*       xBd = g_xB[src ^ 1];

    for (int i = tid; i < HALOH * HALOW; i += TH * TW) {
        int hy = i / HALOW, hx = i % HALOW;
        int gy = ty0 + hy - RAD, gx = tx0 + hx - RAD;
        float a1 = 0.f, a0 = 0.f, b1 = 0.f, b0_ = 0.f;
        if (gy >= 0 && gy < H && gx >= 0 && gx < W) {
            int idx = b * HW + gy * W + gx;
            float xa = xAs[idx];
            float xb = xBs[idx];
            a1 = logf(xa); a0 = logf(1.0f - xa);
            b1 = logf(xb); b0_ = logf(1.0f - xb);
        }
        sA1[hy][hx] = a1; sA0[hy][hx] = a0;
        sB1[hy][hx] = b1; sB0[hy][hx] = b0_;
    }
    __syncthreads();

    int ly = threadIdx.y, lx = threadIdx.x;
    int gy = ty0 + ly, gx = tx0 + lx;
    int hw = gy * W + gx;

    const float* kA = g_kA + (b * NPLANE) * HW + hw;
    const float* kB = g_kB + (b * NPLANE) * HW + hw;

    float S1A = 0.f, S0A = 0.f, S1B = 0.f, S0B = 0.f;
    #pragma unroll
    for (int t = 0; t < NPLANE; t++) {
        const int kh = t / 5, kw = t % 5;
        const int off = (kh - RAD) * W + (kw - RAD);   // o_t flattened (negative)
        float wAf = __ldg(kA + t * HW);
        float wBf = __ldg(kB + t * HW);
        int byy = gy + RAD - kh;                       // p - o_t
        int bxx = gx + RAD - kw;
        bool ok = ((unsigned)byy < H) & ((unsigned)bxx < W);
        float wAb = ok ? __ldg(kA + t * HW - off) : 0.f;
        float wBb = ok ? __ldg(kB + t * HW - off) : 0.f;

        float f1A = sA1[ly + kh][lx + kw], f0A = sA0[ly + kh][lx + kw];
        float f1B = sB1[ly + kh][lx + kw], f0B = sB0[ly + kh][lx + kw];
        float m1A = sA1[ly + 4 - kh][lx + 4 - kw], m0A = sA0[ly + 4 - kh][lx + 4 - kw];
        float m1B = sB1[ly + 4 - kh][lx + 4 - kw], m0B = sB0[ly + 4 - kh][lx + 4 - kw];

        S1A += wAf * f1A + wAb * m1A;
        S0A += wAf * f0A + wAb * m0A;
        S1B += wBf * f1B + wBb * m1B;
        S0B += wBf * f0B + wBb * m0B;
    }
    // center tap: weight exactly exp(0) = 1 for both chains
    S1A += sA1[ly + RAD][lx + RAD];
    S0A += sA0[ly + RAD][lx + RAD];
    S1B += sB1[ly + RAD][lx + RAD];
    S0B += sB0[ly + RAD][lx + RAD];

    {
        float a1 = expf(S1A), a0 = expf(S0A);
        float x = a1 / (1e-6f + (a0 + a1));
        xAd[b * HW + hw] = fminf(fmaxf(x, 0.1f), 0.9f);
    }
    {
        float a1 = expf(S1B), a0 = expf(S0B);
        float x = a1 / (1e-6f + (a0 + a1));
        xBd[b * HW + hw] = fminf(fmaxf(x, 0.1f), 0.9f);
    }
}

// ---------------------------------------------------------------------------
// Finalize: write rgb_mask, accumulate per-batch inter/union for 4 masks.
// ---------------------------------------------------------------------------
__global__ __launch_bounds__(256) void finalize(
    const float* __restrict__ seg, const float* __restrict__ targets,
    const float* __restrict__ sam, int src, float* __restrict__ out_mask) {
    int b = blockIdx.y;
    int p = blockIdx.x * 256 + threadIdx.x;
    int i = b * HW + p;

    bool t  = (targets[i] != 0.f);
    bool m0 = (seg[i]       > 0.5f);
    bool m1 = (g_xA[src][i] > 0.5f);
    bool m2 = (g_xB[src][i] > 0.5f);
    bool m3 = (sam[i] != 0.f);

    out_mask[i] = m1 ? 1.f : 0.f;

    __shared__ unsigned int c[8];
    if (threadIdx.x < 8) c[threadIdx.x] = 0u;
    __syncthreads();

    bool preds[4] = {m0, m1, m2, m3};
    int lane = threadIdx.x & 31;
    #pragma unroll
    for (int m = 0; m < 4; m++) {
        unsigned bi = __ballot_sync(0xFFFFFFFFu, t && preds[m]);
        unsigned bu = __ballot_sync(0xFFFFFFFFu, t || preds[m]);
        if (lane == 0) {
            atomicAdd(&c[2 * m + 0], (unsigned)__popc(bi));
            atomicAdd(&c[2 * m + 1], (unsigned)__popc(bu));
        }
    }
    __syncthreads();
    if (threadIdx.x < 8)
        atomicAdd(&g_cnt[b * 8 + threadIdx.x], c[threadIdx.x]);
}

__global__ void iou_kernel(float* __restrict__ out_ious) {
    int m = threadIdx.x;
    if (m < 4) {
        float s = 0.f;
        for (int b = 0; b < BATCH; b++) {
            float inter = (float)g_cnt[b * 8 + 2 * m + 0];
            float uni   = (float)g_cnt[b * 8 + 2 * m + 1];
            s += inter / (uni + 1e-6f);
        }
        out_ious[m] = s * (1.0f / (float)BATCH);
    }
}

// ---------------------------------------------------------------------------
extern "C" void kernel_launch(void* const* d_in, const int* in_sizes, int n_in,
                              void* d_out, int out_size) {
    const float* fm      = (const float*)d_in[0];  // (16,3,256,256)
    const float* seg     = (const float*)d_in[1];  // (16,256,256)
    const float* depth   = (const float*)d_in[2];
    const float* targets = (const float*)d_in[3];
    const float* sam     = (const float*)d_in[4];
    float* out = (float*)d_out;

    dim3 blk(TW, TH);
    dim3 grd_all(W / TW, H / TH, BATCH);
    dim3 grd_grp(W / TW, H / TH, GB);

    mf_init<<<(BATCH * HW + 255) / 256, 256>>>(seg);
    build_kernels<<<grd_all, blk>>>(fm, depth);

    // L2-blocked schedule: all 10 iterations for GB batches at a time, so
    // weight planes (2 * 12 * GB * 256KB ~ 25 MB) stay L2-resident across iters.
    for (int g = 0; g < BATCH / GB; g++) {
        int src = 0;
        for (int it = 0; it < NITER; it++) {
            mf_iter<<<grd_grp, blk>>>(src, g * GB);
            src ^= 1;
        }
    }

    // after an even number of iterations, final state is in buffer 0
    finalize<<<dim3(HW / 256, BATCH), 256>>>(seg, targets, sam, 0, out);
    iou_kernel<<<1, 32>>>(out + (out_size - 4));
}